// round 5
// baseline (speedup 1.0000x reference)
#include <cuda_runtime.h>
#include <cstdint>

// ---------------------------------------------------------------------------
// SplineCouplingLayer fused kernel (round 3: round-2 design, compile fix)
//  - smem-staged W2/W3, double-buffered k-chunks
//  - strided column ownership (conflict-free LDS.32 for B operand)
//  - packed f32x2 FMA throughout
// ---------------------------------------------------------------------------

#define B_ROWS  131072
#define DIM     64
#define D_IN    32
#define D_OUT   32
#define HIDDEN  512
#define OUTD    736          // 32 * 23
#define TAILB   3.0f

#define TM      32           // rows per block
#define THREADS 256
#define HSTR    34           // padded stride for transposed activations
#define KC      16           // k-chunk for W2/W3 staging

// smem layout (float offsets)
#define OFF_H2   0                                   // 512*34 = 17408
#define OFF_A    17408                               // overlay region
#define OFF_H1   OFF_A                               // phase 2: 17408 fl
#define OFF_W2   (OFF_A + 17408)                     // phase 2: 2*16*512 = 16384 fl
#define OFF_W3   OFF_A                               // phase 3: 2*16*736 = 23552 fl
#define OFF_XT   51200                               // 32*34 = 1088
#define OFF_XM   52288                               // 32*34 = 1088
#define SMEM_FLOATS 53376                            // 213504 bytes

#define W2_CHUNK_F4 2048                             // 16*512/4
#define W3_CHUNK_F4 2944                             // 16*736/4

typedef unsigned long long ull;

__device__ __forceinline__ ull pk(float lo, float hi) {
    ull r; asm("mov.b64 %0, {%1, %2};" : "=l"(r) : "f"(lo), "f"(hi)); return r;
}
__device__ __forceinline__ void unpk(ull v, float &lo, float &hi) {
    asm("mov.b64 {%0, %1}, %2;" : "=f"(lo), "=f"(hi) : "l"(v));
}
// packed 2-wide fp32 FMA (Blackwell): d = a*b + d elementwise on halves
__device__ __forceinline__ void fma2(ull &d, ull a, ull b) {
    asm("fma.rn.f32x2 %0, %1, %2, %0;" : "+l"(d) : "l"(a), "l"(b));
}

// ---------------------------------------------------------------------------
// Spline (register-resident)
// ---------------------------------------------------------------------------
__device__ __forceinline__ float softplusf(float z) {
    return (z > 20.f) ? z : log1pf(expf(z));
}

__device__ __forceinline__ void spline_eval(const float raw[23], float xv,
                                            float &y_out, float &ld_out)
{
    float w[8], h[8];
    float mw = raw[0], mh = raw[8];
#pragma unroll
    for (int i = 1; i < 8; ++i) { mw = fmaxf(mw, raw[i]); mh = fmaxf(mh, raw[8 + i]); }
    float sw = 0.f, sh = 0.f;
#pragma unroll
    for (int i = 0; i < 8; ++i) {
        w[i] = expf(raw[i] - mw);     sw += w[i];
        h[i] = expf(raw[8 + i] - mh); sh += h[i];
    }
    float iw = 6.f / sw, ih = 6.f / sh;
#pragma unroll
    for (int i = 0; i < 8; ++i) { w[i] *= iw; h[i] *= ih; }

    float der[9];
    der[0] = 1.f; der[8] = 1.f;
#pragma unroll
    for (int i = 0; i < 7; ++i) der[i + 1] = softplusf(raw[16 + i]);

    float cw[9], ch[9];
    cw[0] = -TAILB; ch[0] = -TAILB;
#pragma unroll
    for (int i = 0; i < 8; ++i) { cw[i + 1] = cw[i] + w[i]; ch[i + 1] = ch[i] + h[i]; }

    bool inside = (xv >= -TAILB) && (xv <= TAILB);
    float xc = fminf(fmaxf(xv, -TAILB + 1e-6f), TAILB - 1e-6f);

    int idx = 0;
#pragma unroll
    for (int i = 1; i <= 8; ++i) idx += (cw[i] < xc) ? 1 : 0;
    idx = min(idx, 7);

    float wk = w[0], hk = h[0], dk = der[0], dk1 = der[1], cwk = cw[0], chk = ch[0];
#pragma unroll
    for (int i = 1; i < 8; ++i) {
        bool sel = (idx == i);
        wk  = sel ? w[i]      : wk;
        hk  = sel ? h[i]      : hk;
        dk  = sel ? der[i]    : dk;
        dk1 = sel ? der[i + 1]: dk1;
        cwk = sel ? cw[i]     : cwk;
        chk = sel ? ch[i]     : chk;
    }

    float xi = (xc - cwk) / wk;
    xi = fminf(fmaxf(xi, 1e-6f), 1.f - 1e-6f);
    float om = 1.f - xi;
    float s  = hk / wk;
    float num = hk * (s * xi * xi + dk * xi * om);
    float den = s + (dk + dk1 - 2.f * s) * xi * om;
    float yin = chk + num / den;
    float nld = s * s * (dk1 * xi * xi + 2.f * s * xi * om + dk * om * om);
    float ldin = logf(nld + 1e-8f) - logf(den * den + 1e-8f);

    y_out  = inside ? yin  : xv;
    ld_out = inside ? ldin : 0.f;
}

// ---------------------------------------------------------------------------
// Fused kernel
// ---------------------------------------------------------------------------
__global__ void __launch_bounds__(THREADS, 1)
spline_fused(const float* __restrict__ x,
             const float* __restrict__ W1, const float* __restrict__ b1,
             const float* __restrict__ W2, const float* __restrict__ b2,
             const float* __restrict__ W3, const float* __restrict__ b3,
             float* __restrict__ out)
{
    extern __shared__ float sm[];
    const int tid  = threadIdx.x;
    const int row0 = blockIdx.x * TM;

    // thread mapping for layers 1/2 (strided columns: c = cg + 64*j)
    const int cg = tid & 63;
    const int rg = tid >> 6;
    const int r0 = rg * 8;

    // ---- load x tile (transposed); copy masked half straight to output
    for (int idx = tid; idx < TM * DIM; idx += THREADS) {
        int r = idx >> 6, c = idx & 63;
        float v = x[(row0 + r) * DIM + c];
        if (c < D_IN) {
            sm[OFF_XM + c * HSTR + r] = v;
            out[(row0 + r) * DIM + c] = v;
        } else {
            sm[OFF_XT + (c - D_IN) * HSTR + r] = v;
        }
    }
    __syncthreads();

    // =====================================================================
    // Layer 1: h1 = relu(xm @ W1 + b1), K=32, W1 direct from global (small)
    // =====================================================================
    {
        ull acc[8][4];
#pragma unroll
        for (int j = 0; j < 8; ++j) {
            float bv = b1[cg + 64 * j];
            ull bb = pk(bv, bv);
#pragma unroll
            for (int p = 0; p < 4; ++p) acc[j][p] = bb;
        }
#pragma unroll 4
        for (int k = 0; k < D_IN; ++k) {
            ull a2[4];
#pragma unroll
            for (int p = 0; p < 4; ++p)
                a2[p] = *reinterpret_cast<const ull*>(sm + OFF_XM + k * HSTR + r0 + 2 * p);
#pragma unroll
            for (int j = 0; j < 8; ++j) {
                float bv = __ldg(W1 + k * HIDDEN + cg + 64 * j);
                ull bb = pk(bv, bv);
#pragma unroll
                for (int p = 0; p < 4; ++p) fma2(acc[j][p], a2[p], bb);
            }
        }
#pragma unroll
        for (int j = 0; j < 8; ++j)
#pragma unroll
            for (int p = 0; p < 4; ++p) {
                float lo, hi; unpk(acc[j][p], lo, hi);
                *reinterpret_cast<float2*>(sm + OFF_H1 + (cg + 64 * j) * HSTR + r0 + 2 * p)
                    = make_float2(fmaxf(lo, 0.f), fmaxf(hi, 0.f));
            }
    }
    __syncthreads();

    // =====================================================================
    // Layer 2: h2 = relu(h1 @ W2 + b2), K=512, W2 staged in smem (dbl buf)
    // =====================================================================
    {
        ull acc[8][4];
#pragma unroll
        for (int j = 0; j < 8; ++j) {
            float bv = b2[cg + 64 * j];
            ull bb = pk(bv, bv);
#pragma unroll
            for (int p = 0; p < 4; ++p) acc[j][p] = bb;
        }

        // prologue: stage chunk 0
        {
            const float4* src = reinterpret_cast<const float4*>(W2);
            float4* dst = reinterpret_cast<float4*>(sm + OFF_W2);
#pragma unroll
            for (int t = 0; t < 8; ++t) {
                float4 v = __ldg(src + tid + 256 * t);
                dst[tid + 256 * t] = v;
            }
        }
        __syncthreads();

        for (int c = 0; c < HIDDEN / KC; ++c) {
            float4 st[8];
            const bool more = (c + 1 < HIDDEN / KC);
            if (more) {
                const float4* src = reinterpret_cast<const float4*>(W2) + (c + 1) * W2_CHUNK_F4;
#pragma unroll
                for (int t = 0; t < 8; ++t) st[t] = __ldg(src + tid + 256 * t);
            }

            const float* wbuf = sm + OFF_W2 + (c & 1) * (KC * HIDDEN);
            const float* abuf = sm + OFF_H1 + (c * KC) * HSTR;
#pragma unroll 4
            for (int kk = 0; kk < KC; ++kk) {
                ull a2[4];
#pragma unroll
                for (int p = 0; p < 4; ++p)
                    a2[p] = *reinterpret_cast<const ull*>(abuf + kk * HSTR + r0 + 2 * p);
#pragma unroll
                for (int j = 0; j < 8; ++j) {
                    float bv = wbuf[kk * HIDDEN + cg + 64 * j];
                    ull bb = pk(bv, bv);
#pragma unroll
                    for (int p = 0; p < 4; ++p) fma2(acc[j][p], a2[p], bb);
                }
            }

            if (more) {
                float4* dst = reinterpret_cast<float4*>(sm + OFF_W2) + ((c + 1) & 1) * W2_CHUNK_F4;
#pragma unroll
                for (int t = 0; t < 8; ++t) dst[tid + 256 * t] = st[t];
            }
            __syncthreads();
        }

#pragma unroll
        for (int j = 0; j < 8; ++j)
#pragma unroll
            for (int p = 0; p < 4; ++p) {
                float lo, hi; unpk(acc[j][p], lo, hi);
                *reinterpret_cast<float2*>(sm + OFF_H2 + (cg + 64 * j) * HSTR + r0 + 2 * p)
                    = make_float2(fmaxf(lo, 0.f), fmaxf(hi, 0.f));
            }
    }
    __syncthreads();

    // =====================================================================
    // Layer 3: raw = h2 @ W3 + b3, 23 cols x 4 rows per thread, W3 staged
    // =====================================================================
    const int d   = tid & 31;     // spline dim 0..31
    const int rg3 = tid >> 5;     // row group 0..7 (4 rows each)

    ull acc[23][2];
#pragma unroll
    for (int j = 0; j < 23; ++j) {
        float bv = b3[d * 23 + j];
        ull bb = pk(bv, bv);
        acc[j][0] = bb; acc[j][1] = bb;
    }

    // prologue: stage W3 chunk 0
    {
        const float4* src = reinterpret_cast<const float4*>(W3);
        float4* dst = reinterpret_cast<float4*>(sm + OFF_W3);
#pragma unroll
        for (int t = 0; t < 12; ++t) {
            int idx = tid + 256 * t;
            if (idx < W3_CHUNK_F4) dst[idx] = __ldg(src + idx);
        }
    }
    __syncthreads();

    for (int c = 0; c < HIDDEN / KC; ++c) {
        float4 st[12];
        const bool more = (c + 1 < HIDDEN / KC);
        if (more) {
            const float4* src = reinterpret_cast<const float4*>(W3) + (c + 1) * W3_CHUNK_F4;
#pragma unroll
            for (int t = 0; t < 12; ++t) {
                int idx = tid + 256 * t;
                if (idx < W3_CHUNK_F4) st[t] = __ldg(src + idx);
            }
        }

        const float* wbuf = sm + OFF_W3 + (c & 1) * (KC * OUTD);
        const float* abuf = sm + OFF_H2 + (c * KC) * HSTR;
#pragma unroll 2
        for (int kk = 0; kk < KC; ++kk) {
            ull a0 = *reinterpret_cast<const ull*>(abuf + kk * HSTR + rg3 * 4);
            ull a1 = *reinterpret_cast<const ull*>(abuf + kk * HSTR + rg3 * 4 + 2);
            const float* wrow = wbuf + kk * OUTD + d * 23;
#pragma unroll
            for (int j = 0; j < 23; ++j) {
                float bv = wrow[j];        // conflict-free: 23*d distinct mod 32
                ull bb = pk(bv, bv);
                fma2(acc[j][0], a0, bb);
                fma2(acc[j][1], a1, bb);
            }
        }

        if (more) {
            float4* dst = reinterpret_cast<float4*>(sm + OFF_W3) + ((c + 1) & 1) * W3_CHUNK_F4;
#pragma unroll
            for (int t = 0; t < 12; ++t) {
                int idx = tid + 256 * t;
                if (idx < W3_CHUNK_F4) dst[idx] = st[t];
            }
        }
        __syncthreads();
    }

    // ---- spline + output
    float xt_v[4];
#pragma unroll
    for (int i = 0; i < 4; ++i)
        xt_v[i] = sm[OFF_XT + d * HSTR + rg3 * 4 + i];

#pragma unroll
    for (int i = 0; i < 4; ++i) {
        float raw[23];
#pragma unroll
        for (int j = 0; j < 23; ++j) {
            float lo, hi; unpk(acc[j][i >> 1], lo, hi);
            raw[j] = (i & 1) ? hi : lo;
        }
        float yv, ld;
        spline_eval(raw, xt_v[i], yv, ld);

        int gr = row0 + rg3 * 4 + i;
        out[gr * DIM + D_IN + d] = yv;

#pragma unroll
        for (int off = 16; off; off >>= 1)
            ld += __shfl_xor_sync(0xffffffffu, ld, off);
        if (d == 0) out[B_ROWS * DIM + gr] = ld;
    }
}

// ---------------------------------------------------------------------------
extern "C" void kernel_launch(void* const* d_in, const int* in_sizes, int n_in,
                              void* d_out, int out_size)
{
    (void)in_sizes; (void)n_in; (void)out_size;
    const float* x  = (const float*)d_in[0];
    const float* W1 = (const float*)d_in[1];
    const float* b1 = (const float*)d_in[2];
    const float* W2 = (const float*)d_in[3];
    const float* b2 = (const float*)d_in[4];
    const float* W3 = (const float*)d_in[5];
    const float* b3 = (const float*)d_in[6];
    float* out = (float*)d_out;

    size_t smem = SMEM_FLOATS * sizeof(float);  // 213504 B
    cudaFuncSetAttribute(spline_fused,
                         cudaFuncAttributeMaxDynamicSharedMemorySize, (int)smem);
    spline_fused<<<B_ROWS / TM, THREADS, smem>>>(x, W1, b1, W2, b2, W3, b3, out);
}

// round 7
// speedup vs baseline: 1.4234x; 1.4234x over previous
#include <cuda_runtime.h>
#include <cuda_bf16.h>
#include <cstdint>

// ===========================================================================
// SplineCouplingLayer — fused kernel with mma.sync (HMMA) bf16 hi/lo split
// (tcgen05 unavailable: harness targets sm_103 without the 'a' feature)
// ===========================================================================

#define B_ROWS  131072
#define DIM     64
#define D_IN    32
#define HIDDEN  512
#define TAILB   3.0f

#define TM      32            // rows per CTA
#define THREADS 256

// strides (elements)
#define XT_S   33
#define XA_S   40
#define H_S    520
#define ST_S   776

// smem byte offsets (all 16B aligned)
#define SM_XT    0            // 32*33*4   = 4224
#define SM_BIAS  4224         // 768*4     = 3072
#define SM_H2H   7296         // 32*520*2  = 33280
#define SM_H2L   40576
#define SM_WH    73856        // 16*520*2  = 16640
#define SM_WL    90496
#define SM_STASH 107136       // 32*776*4  = 99328 (overlays XA + H1)
#define SM_XAH   107136       // 32*40*2   = 2560
#define SM_XAL   109696
#define SM_H1H   112256       // 33280
#define SM_H1L   145536
#define SM_TOTAL 206464

typedef unsigned int u32;

__device__ __forceinline__ u32 smem_u32(const void* p) {
    u32 a;
    asm("{ .reg .u64 t; cvta.to.shared.u64 t, %1; cvt.u32.u64 %0, t; }"
        : "=r"(a) : "l"(p));
    return a;
}

#define LDSM_X4(r0, r1, r2, r3, a) \
    asm volatile("ldmatrix.sync.aligned.m8n8.x4.shared.b16 {%0,%1,%2,%3}, [%4];" \
                 : "=r"(r0), "=r"(r1), "=r"(r2), "=r"(r3) : "r"(a))
#define LDSM_X4T(r0, r1, r2, r3, a) \
    asm volatile("ldmatrix.sync.aligned.m8n8.x4.trans.shared.b16 {%0,%1,%2,%3}, [%4];" \
                 : "=r"(r0), "=r"(r1), "=r"(r2), "=r"(r3) : "r"(a))

__device__ __forceinline__ void mma_bf16(float* c, const u32* a, u32 b0, u32 b1) {
    asm volatile(
        "mma.sync.aligned.m16n8k16.row.col.f32.bf16.bf16.f32 "
        "{%0,%1,%2,%3},{%4,%5,%6,%7},{%8,%9},{%0,%1,%2,%3};"
        : "+f"(c[0]), "+f"(c[1]), "+f"(c[2]), "+f"(c[3])
        : "r"(a[0]), "r"(a[1]), "r"(a[2]), "r"(a[3]), "r"(b0), "r"(b1));
}

__device__ __forceinline__ u32 pk2(__nv_bfloat16 a, __nv_bfloat16 b) {
    return (u32)__bfloat16_as_ushort(a) | ((u32)__bfloat16_as_ushort(b) << 16);
}
__device__ __forceinline__ void split2(float x, float y, u32 &hi, u32 &lo) {
    __nv_bfloat16 xh = __float2bfloat16_rn(x);
    __nv_bfloat16 yh = __float2bfloat16_rn(y);
    __nv_bfloat16 xl = __float2bfloat16_rn(x - __bfloat162float(xh));
    __nv_bfloat16 yl = __float2bfloat16_rn(y - __bfloat162float(yh));
    hi = pk2(xh, yh);
    lo = pk2(xl, yl);
}

// ---------------------------------------------------------------------------
// One layer: out = act(A @ W + bias).  A: smem bf16 hi/lo, row-major [32][K].
// W: global fp32 [K][WFULL], cols [wcol0, wcol0+CW) staged per 16-k chunk.
// NW: n-cols per warp. Output either bf16 hi/lo H arrays or fp32 stash.
// ---------------------------------------------------------------------------
template<int NW, int NCH, bool RELU, bool STASH>
__device__ __forceinline__ void do_layer(
    char* sm, u32 smb, int tid,
    const float* __restrict__ Wg, int WFULL, int wcol0, int nvalid,
    const float* __restrict__ biasg,
    int aoff_h, int aoff_l, int AS,
    int hoff_h, int hoff_l, int stash_col0)
{
    constexpr int NT  = NW / 8;        // n-tiles per warp
    constexpr int CW  = NW * 8;        // staged cols (all 8 warps)
    constexpr int CW4 = CW / 4;
    constexpr int LD  = 16 * CW4 / 256;
    constexpr int WS  = CW + 8;        // stage stride (elems)

    const int wid = tid >> 5, lane = tid & 31;
    float* bias_sm = (float*)(sm + SM_BIAS);

    for (int i = tid; i < CW; i += 256) {
        int gc = wcol0 + i;
        bias_sm[i] = (gc < nvalid) ? biasg[gc] : 0.f;
    }

    float acc[2][NT][4];
#pragma unroll
    for (int mt = 0; mt < 2; ++mt)
#pragma unroll
        for (int nt = 0; nt < NT; ++nt)
#pragma unroll
            for (int q = 0; q < 4; ++q) acc[mt][nt][q] = 0.f;

    float4 st[LD];
    // prefetch chunk 0
#pragma unroll
    for (int t = 0; t < LD; ++t) {
        int idx = tid + 256 * t;
        int r = idx / CW4, c4 = idx % CW4;
        int gc = wcol0 + c4 * 4;
        st[t] = (gc < nvalid)
              ? *(const float4*)(Wg + (size_t)r * WFULL + gc)
              : make_float4(0.f, 0.f, 0.f, 0.f);
    }

    for (int c = 0; c < NCH; ++c) {
        __syncthreads();                    // W buffer free / A ready
#pragma unroll
        for (int t = 0; t < LD; ++t) {
            int idx = tid + 256 * t;
            int r = idx / CW4, c4 = idx % CW4;
            u32 h01, l01, h23, l23;
            split2(st[t].x, st[t].y, h01, l01);
            split2(st[t].z, st[t].w, h23, l23);
            u32 off = (u32)(r * WS + c4 * 4) * 2;
            *(uint2*)(sm + SM_WH + off) = make_uint2(h01, h23);
            *(uint2*)(sm + SM_WL + off) = make_uint2(l01, l23);
        }
        __syncthreads();                    // W visible

        if (c + 1 < NCH) {
            int k0 = (c + 1) * 16;
#pragma unroll
            for (int t = 0; t < LD; ++t) {
                int idx = tid + 256 * t;
                int r = idx / CW4, c4 = idx % CW4;
                int gc = wcol0 + c4 * 4;
                st[t] = (gc < nvalid)
                      ? *(const float4*)(Wg + (size_t)(k0 + r) * WFULL + gc)
                      : make_float4(0.f, 0.f, 0.f, 0.f);
            }
        }

        // ---- A fragments (hi & lo), 2 m-tiles ----
        const int cK = c * 16;
        u32 ah[2][4], al[2][4];
#pragma unroll
        for (int mt = 0; mt < 2; ++mt) {
            int r  = mt * 16 + (lane & 7) + ((lane >> 3) & 1) * 8;
            int cc = cK + (lane >> 4) * 8;
            u32 off = (u32)(r * AS + cc) * 2;
            LDSM_X4(ah[mt][0], ah[mt][1], ah[mt][2], ah[mt][3], smb + aoff_h + off);
            LDSM_X4(al[mt][0], al[mt][1], al[mt][2], al[mt][3], smb + aoff_l + off);
        }

        const int rk    = (lane & 7) + ((lane >> 3) & 1) * 8;
        const int cbase = wid * NW + (lane >> 4) * 8;

        // ---- B hi, passes ah*bh and al*bh ----
        {
            u32 bh[NT][2];
#pragma unroll
            for (int i = 0; i < NT / 2; ++i) {
                u32 a4 = smb + SM_WH + (u32)(rk * WS + cbase + i * 16) * 2;
                u32 r0, r1, r2, r3;
                LDSM_X4T(r0, r1, r2, r3, a4);
                bh[2 * i][0] = r0; bh[2 * i][1] = r1;
                bh[2 * i + 1][0] = r2; bh[2 * i + 1][1] = r3;
            }
#pragma unroll
            for (int mt = 0; mt < 2; ++mt)
#pragma unroll
                for (int nt = 0; nt < NT; ++nt)
                    mma_bf16(acc[mt][nt], ah[mt], bh[nt][0], bh[nt][1]);
#pragma unroll
            for (int mt = 0; mt < 2; ++mt)
#pragma unroll
                for (int nt = 0; nt < NT; ++nt)
                    mma_bf16(acc[mt][nt], al[mt], bh[nt][0], bh[nt][1]);
        }
        // ---- B lo, pass ah*bl ----
        {
            u32 bl[NT][2];
#pragma unroll
            for (int i = 0; i < NT / 2; ++i) {
                u32 a4 = smb + SM_WL + (u32)(rk * WS + cbase + i * 16) * 2;
                u32 r0, r1, r2, r3;
                LDSM_X4T(r0, r1, r2, r3, a4);
                bl[2 * i][0] = r0; bl[2 * i][1] = r1;
                bl[2 * i + 1][0] = r2; bl[2 * i + 1][1] = r3;
            }
#pragma unroll
            for (int mt = 0; mt < 2; ++mt)
#pragma unroll
                for (int nt = 0; nt < NT; ++nt)
                    mma_bf16(acc[mt][nt], ah[mt], bl[nt][0], bl[nt][1]);
        }
    }
    __syncthreads();

    // ---- epilogue ----
    const int g  = lane >> 2;
    const int t2 = (lane & 3) * 2;
#pragma unroll
    for (int mt = 0; mt < 2; ++mt)
#pragma unroll
        for (int nt = 0; nt < NT; ++nt) {
            int col = wid * NW + nt * 8 + t2;
            float b0v = bias_sm[col], b1v = bias_sm[col + 1];
            float v0 = acc[mt][nt][0] + b0v, v1 = acc[mt][nt][1] + b1v;
            float v2 = acc[mt][nt][2] + b0v, v3 = acc[mt][nt][3] + b1v;
            int rA = mt * 16 + g, rB = rA + 8;
            if (STASH) {
                *(float2*)(sm + SM_STASH + ((u32)rA * ST_S + stash_col0 + col) * 4)
                    = make_float2(v0, v1);
                *(float2*)(sm + SM_STASH + ((u32)rB * ST_S + stash_col0 + col) * 4)
                    = make_float2(v2, v3);
            } else {
                if (RELU) {
                    v0 = fmaxf(v0, 0.f); v1 = fmaxf(v1, 0.f);
                    v2 = fmaxf(v2, 0.f); v3 = fmaxf(v3, 0.f);
                }
                u32 h01, l01, h23, l23;
                split2(v0, v1, h01, l01);
                split2(v2, v3, h23, l23);
                u32 oA = (u32)(rA * H_S + col) * 2;
                u32 oB = (u32)(rB * H_S + col) * 2;
                *(u32*)(sm + hoff_h + oA) = h01;
                *(u32*)(sm + hoff_l + oA) = l01;
                *(u32*)(sm + hoff_h + oB) = h23;
                *(u32*)(sm + hoff_l + oB) = l23;
            }
        }
}

// ---------------------------------------------------------------------------
// Spline (verified math from round 1)
// ---------------------------------------------------------------------------
__device__ __forceinline__ float softplusf(float z) {
    return (z > 20.f) ? z : log1pf(expf(z));
}
__device__ __forceinline__ void spline_eval(const float raw[23], float xv,
                                            float &y_out, float &ld_out)
{
    float w[8], h[8];
    float mw = raw[0], mh = raw[8];
#pragma unroll
    for (int i = 1; i < 8; ++i) { mw = fmaxf(mw, raw[i]); mh = fmaxf(mh, raw[8 + i]); }
    float sw = 0.f, sh = 0.f;
#pragma unroll
    for (int i = 0; i < 8; ++i) {
        w[i] = expf(raw[i] - mw); sw += w[i];
        h[i] = expf(raw[8 + i] - mh); sh += h[i];
    }
    float iw = 6.f / sw, ih = 6.f / sh;
#pragma unroll
    for (int i = 0; i < 8; ++i) { w[i] *= iw; h[i] *= ih; }
    float der[9]; der[0] = 1.f; der[8] = 1.f;
#pragma unroll
    for (int i = 0; i < 7; ++i) der[i + 1] = softplusf(raw[16 + i]);
    float cw[9], ch[9]; cw[0] = -TAILB; ch[0] = -TAILB;
#pragma unroll
    for (int i = 0; i < 8; ++i) { cw[i + 1] = cw[i] + w[i]; ch[i + 1] = ch[i] + h[i]; }
    bool inside = (xv >= -TAILB) && (xv <= TAILB);
    float xc = fminf(fmaxf(xv, -TAILB + 1e-6f), TAILB - 1e-6f);
    int idx = 0;
#pragma unroll
    for (int i = 1; i <= 8; ++i) idx += (cw[i] < xc) ? 1 : 0;
    idx = min(idx, 7);
    float wk = w[0], hk = h[0], dk = der[0], dk1 = der[1], cwk = cw[0], chk = ch[0];
#pragma unroll
    for (int i = 1; i < 8; ++i) {
        bool sel = (idx == i);
        wk = sel ? w[i] : wk;   hk = sel ? h[i] : hk;
        dk = sel ? der[i] : dk; dk1 = sel ? der[i + 1] : dk1;
        cwk = sel ? cw[i] : cwk; chk = sel ? ch[i] : chk;
    }
    float xi = fminf(fmaxf((xc - cwk) / wk, 1e-6f), 1.f - 1e-6f);
    float om = 1.f - xi;
    float s = hk / wk;
    float num = hk * (s * xi * xi + dk * xi * om);
    float den = s + (dk + dk1 - 2.f * s) * xi * om;
    float yin = chk + num / den;
    float nld = s * s * (dk1 * xi * xi + 2.f * s * xi * om + dk * om * om);
    float ldin = logf(nld + 1e-8f) - logf(den * den + 1e-8f);
    y_out = inside ? yin : xv;
    ld_out = inside ? ldin : 0.f;
}

// ---------------------------------------------------------------------------
__global__ void __launch_bounds__(THREADS, 1)
spline_fused(const float* __restrict__ x,
             const float* __restrict__ W1, const float* __restrict__ b1,
             const float* __restrict__ W2, const float* __restrict__ b2,
             const float* __restrict__ W3, const float* __restrict__ b3,
             float* __restrict__ out)
{
    extern __shared__ char sm[];
    const u32 smb = smem_u32(sm);
    const int tid  = threadIdx.x;
    const int wid  = tid >> 5, lane = tid & 31;
    const int row0 = blockIdx.x * TM;

    // ---- load x tile: masked -> XA hi/lo + passthrough; transform -> XT ----
    for (int idx = tid; idx < TM * DIM; idx += THREADS) {
        int r = idx >> 6, c = idx & 63;
        float v = x[(size_t)(row0 + r) * DIM + c];
        if (c < D_IN) {
            out[(size_t)(row0 + r) * DIM + c] = v;
            __nv_bfloat16 hh = __float2bfloat16_rn(v);
            __nv_bfloat16 ll = __float2bfloat16_rn(v - __bfloat162float(hh));
            *(__nv_bfloat16*)(sm + SM_XAH + (u32)(r * XA_S + c) * 2) = hh;
            *(__nv_bfloat16*)(sm + SM_XAL + (u32)(r * XA_S + c) * 2) = ll;
        } else {
            *(float*)(sm + SM_XT + (u32)(r * XT_S + (c - D_IN)) * 4) = v;
        }
    }
    __syncthreads();

    // layer 1: K=32, N=512, relu -> H1
    do_layer<64, 2, true, false>(sm, smb, tid, W1, 512, 0, 512, b1,
                                 SM_XAH, SM_XAL, XA_S, SM_H1H, SM_H1L, 0);
    __syncthreads();
    // layer 2: K=512, N=512, relu -> H2
    do_layer<64, 32, true, false>(sm, smb, tid, W2, 512, 0, 512, b2,
                                  SM_H1H, SM_H1L, H_S, SM_H2H, SM_H2L, 0);
    __syncthreads();
    // layer 3: K=512, N=736 (two halves of 384) -> fp32 stash
    do_layer<48, 32, false, true>(sm, smb, tid, W3, 736, 0, 736, b3,
                                  SM_H2H, SM_H2L, H_S, 0, 0, 0);
    __syncthreads();
    do_layer<48, 32, false, true>(sm, smb, tid, W3, 736, 384, 736, b3,
                                  SM_H2H, SM_H2L, H_S, 0, 0, 384);
    __syncthreads();

    // ---- spline: warp w handles rows {w, w+8, w+16, w+24}, lane = dim ----
    const float* stashf = (const float*)(sm + SM_STASH);
    const float* xtf    = (const float*)(sm + SM_XT);
#pragma unroll
    for (int it = 0; it < 4; ++it) {
        int row = wid + it * 8;
        int d   = lane;
        float raw[23];
        const float* rp = stashf + (u32)row * ST_S + d * 23;
#pragma unroll
        for (int j = 0; j < 23; ++j) raw[j] = rp[j];
        float xv = xtf[row * XT_S + d];
        float yv, ld;
        spline_eval(raw, xv, yv, ld);
        int gr = row0 + row;
        out[(size_t)gr * DIM + D_IN + d] = yv;
#pragma unroll
        for (int off = 16; off; off >>= 1)
            ld += __shfl_xor_sync(0xffffffffu, ld, off);
        if (d == 0) out[(size_t)B_ROWS * DIM + gr] = ld;
    }
}

// ---------------------------------------------------------------------------
extern "C" void kernel_launch(void* const* d_in, const int* in_sizes, int n_in,
                              void* d_out, int out_size)
{
    (void)in_sizes; (void)n_in; (void)out_size;
    const float* x  = (const float*)d_in[0];
    const float* W1 = (const float*)d_in[1];
    const float* b1 = (const float*)d_in[2];
    const float* W2 = (const float*)d_in[3];
    const float* b2 = (const float*)d_in[4];
    const float* W3 = (const float*)d_in[5];
    const float* b3 = (const float*)d_in[6];
    float* out = (float*)d_out;

    cudaFuncSetAttribute(spline_fused,
                         cudaFuncAttributeMaxDynamicSharedMemorySize, SM_TOTAL);
    spline_fused<<<B_ROWS / TM, THREADS, SM_TOTAL>>>(x, W1, b1, W2, b2, W3, b3, out);
}

// round 8
// speedup vs baseline: 2.2031x; 1.5478x over previous
#include <cuda_runtime.h>
#include <cuda_bf16.h>
#include <cstdint>

// ===========================================================================
// SplineCouplingLayer — fused HMMA bf16 hi/lo split, 16 warps, pre-split W
// ===========================================================================

#define B_ROWS  131072
#define DIM     64
#define D_IN    32
#define HIDDEN  512
#define TAILB   3.0f

#define TM      32
#define THREADS 512

// strides (elements)
#define XT_S   33
#define XA_S   40
#define H_S    520
#define ST_S   776

// smem byte offsets
#define SM_XT    0            // 32*33*4  = 4224
#define SM_BIAS  4224         // 512*4    = 2048
#define SM_H2H   6272         // 32*520*2 = 33280
#define SM_H2L   39552        // 33280
#define SM_WH    72832        // 16*520*2 = 16640
#define SM_WL    89472        // 16640
#define SM_XAH   106112       // 2560
#define SM_XAL   108672       // 2560
#define SM_H1H   111232       // 33280
#define SM_H1L   144512       // 33280
#define SM_STASH 106112       // 32*776*4 = 99328 (overlays XA/H1)
#define SM_TOTAL 205440

typedef unsigned int u32;

// pre-split weights (bf16 hi/lo), W3 padded to 768 cols
__device__ __nv_bfloat16 g_W1h[32 * 512],  g_W1l[32 * 512];
__device__ __nv_bfloat16 g_W2h[512 * 512], g_W2l[512 * 512];
__device__ __nv_bfloat16 g_W3h[512 * 768], g_W3l[512 * 768];

__device__ __forceinline__ u32 smem_u32(const void* p) {
    u32 a;
    asm("{ .reg .u64 t; cvta.to.shared.u64 t, %1; cvt.u32.u64 %0, t; }"
        : "=r"(a) : "l"(p));
    return a;
}

#define LDSM_X4(r0, r1, r2, r3, a) \
    asm volatile("ldmatrix.sync.aligned.m8n8.x4.shared.b16 {%0,%1,%2,%3}, [%4];" \
                 : "=r"(r0), "=r"(r1), "=r"(r2), "=r"(r3) : "r"(a))
#define LDSM_X4T(r0, r1, r2, r3, a) \
    asm volatile("ldmatrix.sync.aligned.m8n8.x4.trans.shared.b16 {%0,%1,%2,%3}, [%4];" \
                 : "=r"(r0), "=r"(r1), "=r"(r2), "=r"(r3) : "r"(a))
#define LDSM_X2T(r0, r1, a) \
    asm volatile("ldmatrix.sync.aligned.m8n8.x2.trans.shared.b16 {%0,%1}, [%2];" \
                 : "=r"(r0), "=r"(r1) : "r"(a))

__device__ __forceinline__ void mma_bf16(float* c, const u32* a, u32 b0, u32 b1) {
    asm volatile(
        "mma.sync.aligned.m16n8k16.row.col.f32.bf16.bf16.f32 "
        "{%0,%1,%2,%3},{%4,%5,%6,%7},{%8,%9},{%0,%1,%2,%3};"
        : "+f"(c[0]), "+f"(c[1]), "+f"(c[2]), "+f"(c[3])
        : "r"(a[0]), "r"(a[1]), "r"(a[2]), "r"(a[3]), "r"(b0), "r"(b1));
}

__device__ __forceinline__ u32 pk2(__nv_bfloat16 a, __nv_bfloat16 b) {
    return (u32)__bfloat16_as_ushort(a) | ((u32)__bfloat16_as_ushort(b) << 16);
}
__device__ __forceinline__ void split2(float x, float y, u32 &hi, u32 &lo) {
    __nv_bfloat16 xh = __float2bfloat16_rn(x);
    __nv_bfloat16 yh = __float2bfloat16_rn(y);
    __nv_bfloat16 xl = __float2bfloat16_rn(x - __bfloat162float(xh));
    __nv_bfloat16 yl = __float2bfloat16_rn(y - __bfloat162float(yh));
    hi = pk2(xh, yh);
    lo = pk2(xl, yl);
}

// ---------------------------------------------------------------------------
// One layer (16 warps). A: smem bf16 hi/lo [32][K] stride AS. W: pre-split
// global bf16 [K][WFULL], cols [wcol0, wcol0+CW). NW cols per warp.
// ---------------------------------------------------------------------------
template<int NW, int NCH, bool RELU, bool STASH>
__device__ __forceinline__ void do_layer(
    char* sm, u32 smb, int tid,
    const __nv_bfloat16* __restrict__ Wh, const __nv_bfloat16* __restrict__ Wl,
    int WFULL, int wcol0,
    const float* __restrict__ biasg, int nbias,
    int aoff_h, int aoff_l, int AS,
    int hoff_h, int hoff_l, int stash_col0)
{
    constexpr int NT   = NW / 8;
    constexpr int CW   = NW * 16;           // cols staged (16 warps)
    constexpr int WS   = CW + 8;
    constexpr int C8   = CW / 8;            // uint4 per k-row
    constexpr int U4T  = 16 * C8;           // uint4 per buffer
    constexpr int U4IT = (U4T + THREADS - 1) / THREADS;

    const int wid = tid >> 5, lane = tid & 31;
    float* bias_sm = (float*)(sm + SM_BIAS);
    for (int i = tid; i < CW; i += THREADS) {
        int gc = wcol0 + i;
        bias_sm[i] = (gc < nbias) ? biasg[gc] : 0.f;
    }

    float acc[2][NT][4];
#pragma unroll
    for (int mt = 0; mt < 2; ++mt)
#pragma unroll
        for (int nt = 0; nt < NT; ++nt)
#pragma unroll
            for (int q = 0; q < 4; ++q) acc[mt][nt][q] = 0.f;

    uint4 preH[U4IT], preL[U4IT];
    // prefetch chunk 0
#pragma unroll
    for (int t = 0; t < U4IT; ++t) {
        int idx = tid + THREADS * t;
        if (U4T % THREADS == 0 || idx < U4T) {
            int r = idx / C8, c8 = idx % C8;
            size_t g = (size_t)r * WFULL + wcol0 + c8 * 8;
            preH[t] = *(const uint4*)(Wh + g);
            preL[t] = *(const uint4*)(Wl + g);
        }
    }

    for (int c = 0; c < NCH; ++c) {
        __syncthreads();                         // W buffer free
#pragma unroll
        for (int t = 0; t < U4IT; ++t) {
            int idx = tid + THREADS * t;
            if (U4T % THREADS == 0 || idx < U4T) {
                int r = idx / C8, c8 = idx % C8;
                u32 off = (u32)(r * WS + c8 * 8) * 2;
                *(uint4*)(sm + SM_WH + off) = preH[t];
                *(uint4*)(sm + SM_WL + off) = preL[t];
            }
        }
        __syncthreads();                         // W visible

        if (c + 1 < NCH) {
            int k0 = (c + 1) * 16;
#pragma unroll
            for (int t = 0; t < U4IT; ++t) {
                int idx = tid + THREADS * t;
                if (U4T % THREADS == 0 || idx < U4T) {
                    int r = idx / C8, c8 = idx % C8;
                    size_t g = (size_t)(k0 + r) * WFULL + wcol0 + c8 * 8;
                    preH[t] = *(const uint4*)(Wh + g);
                    preL[t] = *(const uint4*)(Wl + g);
                }
            }
        }

        // ---- A fragments ----
        const int cK = c * 16;
        u32 ah[2][4], al[2][4];
#pragma unroll
        for (int mt = 0; mt < 2; ++mt) {
            int r  = mt * 16 + (lane & 7) + ((lane >> 3) & 1) * 8;
            int cc = cK + (lane >> 4) * 8;
            u32 off = (u32)(r * AS + cc) * 2;
            LDSM_X4(ah[mt][0], ah[mt][1], ah[mt][2], ah[mt][3], smb + aoff_h + off);
            LDSM_X4(al[mt][0], al[mt][1], al[mt][2], al[mt][3], smb + aoff_l + off);
        }

        const int rk  = (lane & 7) + ((lane >> 3) & 1) * 8;
        const int cb0 = wid * NW;

        // ---- B hi: ah*bh + al*bh ----
        {
            u32 bh[NT][2];
#pragma unroll
            for (int i = 0; i < NT / 2; ++i) {
                u32 a4 = smb + SM_WH + (u32)(rk * WS + cb0 + (lane >> 4) * 8 + i * 16) * 2;
                u32 r0, r1, r2, r3;
                LDSM_X4T(r0, r1, r2, r3, a4);
                bh[2 * i][0] = r0; bh[2 * i][1] = r1;
                bh[2 * i + 1][0] = r2; bh[2 * i + 1][1] = r3;
            }
            if (NT & 1) {
                u32 a2 = smb + SM_WH + (u32)(rk * WS + cb0 + (NT - 1) * 8) * 2;
                LDSM_X2T(bh[NT - 1][0], bh[NT - 1][1], a2);
            }
#pragma unroll
            for (int mt = 0; mt < 2; ++mt)
#pragma unroll
                for (int nt = 0; nt < NT; ++nt)
                    mma_bf16(acc[mt][nt], ah[mt], bh[nt][0], bh[nt][1]);
#pragma unroll
            for (int mt = 0; mt < 2; ++mt)
#pragma unroll
                for (int nt = 0; nt < NT; ++nt)
                    mma_bf16(acc[mt][nt], al[mt], bh[nt][0], bh[nt][1]);
        }
        // ---- B lo: ah*bl ----
        {
            u32 bl[NT][2];
#pragma unroll
            for (int i = 0; i < NT / 2; ++i) {
                u32 a4 = smb + SM_WL + (u32)(rk * WS + cb0 + (lane >> 4) * 8 + i * 16) * 2;
                u32 r0, r1, r2, r3;
                LDSM_X4T(r0, r1, r2, r3, a4);
                bl[2 * i][0] = r0; bl[2 * i][1] = r1;
                bl[2 * i + 1][0] = r2; bl[2 * i + 1][1] = r3;
            }
            if (NT & 1) {
                u32 a2 = smb + SM_WL + (u32)(rk * WS + cb0 + (NT - 1) * 8) * 2;
                LDSM_X2T(bl[NT - 1][0], bl[NT - 1][1], a2);
            }
#pragma unroll
            for (int mt = 0; mt < 2; ++mt)
#pragma unroll
                for (int nt = 0; nt < NT; ++nt)
                    mma_bf16(acc[mt][nt], ah[mt], bl[nt][0], bl[nt][1]);
        }
    }
    __syncthreads();

    // ---- epilogue ----
    const int g  = lane >> 2;
    const int t2 = (lane & 3) * 2;
#pragma unroll
    for (int mt = 0; mt < 2; ++mt)
#pragma unroll
        for (int nt = 0; nt < NT; ++nt) {
            int col = wid * NW + nt * 8 + t2;
            float b0v = bias_sm[col], b1v = bias_sm[col + 1];
            float v0 = acc[mt][nt][0] + b0v, v1 = acc[mt][nt][1] + b1v;
            float v2 = acc[mt][nt][2] + b0v, v3 = acc[mt][nt][3] + b1v;
            int rA = mt * 16 + g, rB = rA + 8;
            if (STASH) {
                *(float2*)(sm + SM_STASH + ((u32)rA * ST_S + stash_col0 + col) * 4)
                    = make_float2(v0, v1);
                *(float2*)(sm + SM_STASH + ((u32)rB * ST_S + stash_col0 + col) * 4)
                    = make_float2(v2, v3);
            } else {
                if (RELU) {
                    v0 = fmaxf(v0, 0.f); v1 = fmaxf(v1, 0.f);
                    v2 = fmaxf(v2, 0.f); v3 = fmaxf(v3, 0.f);
                }
                u32 h01, l01, h23, l23;
                split2(v0, v1, h01, l01);
                split2(v2, v3, h23, l23);
                u32 oA = (u32)(rA * H_S + col) * 2;
                u32 oB = (u32)(rB * H_S + col) * 2;
                *(u32*)(sm + hoff_h + oA) = h01;
                *(u32*)(sm + hoff_l + oA) = l01;
                *(u32*)(sm + hoff_h + oB) = h23;
                *(u32*)(sm + hoff_l + oB) = l23;
            }
        }
}

// ---------------------------------------------------------------------------
__device__ __forceinline__ float softplusf(float z) {
    return (z > 20.f) ? z : log1pf(expf(z));
}
__device__ __forceinline__ void spline_eval(const float raw[23], float xv,
                                            float &y_out, float &ld_out)
{
    float w[8], h[8];
    float mw = raw[0], mh = raw[8];
#pragma unroll
    for (int i = 1; i < 8; ++i) { mw = fmaxf(mw, raw[i]); mh = fmaxf(mh, raw[8 + i]); }
    float sw = 0.f, sh = 0.f;
#pragma unroll
    for (int i = 0; i < 8; ++i) {
        w[i] = expf(raw[i] - mw); sw += w[i];
        h[i] = expf(raw[8 + i] - mh); sh += h[i];
    }
    float iw = 6.f / sw, ih = 6.f / sh;
#pragma unroll
    for (int i = 0; i < 8; ++i) { w[i] *= iw; h[i] *= ih; }
    float der[9]; der[0] = 1.f; der[8] = 1.f;
#pragma unroll
    for (int i = 0; i < 7; ++i) der[i + 1] = softplusf(raw[16 + i]);
    float cw[9], ch[9]; cw[0] = -TAILB; ch[0] = -TAILB;
#pragma unroll
    for (int i = 0; i < 8; ++i) { cw[i + 1] = cw[i] + w[i]; ch[i + 1] = ch[i] + h[i]; }
    bool inside = (xv >= -TAILB) && (xv <= TAILB);
    float xc = fminf(fmaxf(xv, -TAILB + 1e-6f), TAILB - 1e-6f);
    int idx = 0;
#pragma unroll
    for (int i = 1; i <= 8; ++i) idx += (cw[i] < xc) ? 1 : 0;
    idx = min(idx, 7);
    float wk = w[0], hk = h[0], dk = der[0], dk1 = der[1], cwk = cw[0], chk = ch[0];
#pragma unroll
    for (int i = 1; i < 8; ++i) {
        bool sel = (idx == i);
        wk = sel ? w[i] : wk;   hk = sel ? h[i] : hk;
        dk = sel ? der[i] : dk; dk1 = sel ? der[i + 1] : dk1;
        cwk = sel ? cw[i] : cwk; chk = sel ? ch[i] : chk;
    }
    float xi = fminf(fmaxf((xc - cwk) / wk, 1e-6f), 1.f - 1e-6f);
    float om = 1.f - xi;
    float s = hk / wk;
    float num = hk * (s * xi * xi + dk * xi * om);
    float den = s + (dk + dk1 - 2.f * s) * xi * om;
    float yin = chk + num / den;
    float nld = s * s * (dk1 * xi * xi + 2.f * s * xi * om + dk * om * om);
    float ldin = logf(nld + 1e-8f) - logf(den * den + 1e-8f);
    y_out = inside ? yin : xv;
    ld_out = inside ? ldin : 0.f;
}

// ---------------------------------------------------------------------------
__global__ void __launch_bounds__(THREADS, 1)
spline_fused(const float* __restrict__ x,
             const float* __restrict__ b1, const float* __restrict__ b2,
             const float* __restrict__ b3, float* __restrict__ out)
{
    extern __shared__ char sm[];
    const u32 smb = smem_u32(sm);
    const int tid  = threadIdx.x;
    const int wid  = tid >> 5, lane = tid & 31;
    const int row0 = blockIdx.x * TM;

    // load x tile: masked -> XA hi/lo + passthrough; transform -> XT
    for (int idx = tid; idx < TM * DIM; idx += THREADS) {
        int r = idx >> 6, c = idx & 63;
        float v = x[(size_t)(row0 + r) * DIM + c];
        if (c < D_IN) {
            out[(size_t)(row0 + r) * DIM + c] = v;
            __nv_bfloat16 hh = __float2bfloat16_rn(v);
            __nv_bfloat16 ll = __float2bfloat16_rn(v - __bfloat162float(hh));
            *(__nv_bfloat16*)(sm + SM_XAH + (u32)(r * XA_S + c) * 2) = hh;
            *(__nv_bfloat16*)(sm + SM_XAL + (u32)(r * XA_S + c) * 2) = ll;
        } else {
            *(float*)(sm + SM_XT + (u32)(r * XT_S + (c - D_IN)) * 4) = v;
        }
    }
    __syncthreads();

    // layer 1: K=32, N=512
    do_layer<32, 2, true, false>(sm, smb, tid, g_W1h, g_W1l, 512, 0,
                                 b1, 512, SM_XAH, SM_XAL, XA_S, SM_H1H, SM_H1L, 0);
    __syncthreads();
    // layer 2: K=512, N=512
    do_layer<32, 32, true, false>(sm, smb, tid, g_W2h, g_W2l, 512, 0,
                                  b2, 512, SM_H1H, SM_H1L, H_S, SM_H2H, SM_H2L, 0);
    __syncthreads();
    // layer 3: K=512, N=736/768 in two 384-col passes -> fp32 stash
    do_layer<24, 32, false, true>(sm, smb, tid, g_W3h, g_W3l, 768, 0,
                                  b3, 736, SM_H2H, SM_H2L, H_S, 0, 0, 0);
    __syncthreads();
    do_layer<24, 32, false, true>(sm, smb, tid, g_W3h, g_W3l, 768, 384,
                                  b3, 736, SM_H2H, SM_H2L, H_S, 0, 0, 384);
    __syncthreads();

    // spline: warp w -> rows {w, w+16}
    const float* stashf = (const float*)(sm + SM_STASH);
    const float* xtf    = (const float*)(sm + SM_XT);
#pragma unroll
    for (int it = 0; it < 2; ++it) {
        int row = wid + it * 16;
        int d   = lane;
        float raw[23];
        const float* rp = stashf + (u32)row * ST_S + d * 23;
#pragma unroll
        for (int j = 0; j < 23; ++j) raw[j] = rp[j];
        float xv = xtf[row * XT_S + d];
        float yv, ld;
        spline_eval(raw, xv, yv, ld);
        int gr = row0 + row;
        out[(size_t)gr * DIM + D_IN + d] = yv;
#pragma unroll
        for (int off = 16; off; off >>= 1)
            ld += __shfl_xor_sync(0xffffffffu, ld, off);
        if (d == 0) out[(size_t)B_ROWS * DIM + gr] = ld;
    }
}

// ---------------------------------------------------------------------------
// prep: split W into bf16 hi/lo globals (W3 padded to 768 cols)
// ---------------------------------------------------------------------------
__global__ void __launch_bounds__(256)
prep_kernel(const float* __restrict__ W1, const float* __restrict__ W2,
            const float* __restrict__ W3)
{
    const int N1 = 32 * 512, N2 = 512 * 512, N3 = 512 * 768;
    const int TOT = N1 + N2 + N3;
    for (int idx = blockIdx.x * 256 + threadIdx.x; idx < TOT;
         idx += gridDim.x * 256) {
        float v; __nv_bfloat16 *ph, *pl; int o;
        if (idx < N1) {
            o = idx; v = W1[o]; ph = g_W1h; pl = g_W1l;
        } else if (idx < N1 + N2) {
            o = idx - N1; v = W2[o]; ph = g_W2h; pl = g_W2l;
        } else {
            o = idx - N1 - N2;
            int k = o / 768, n = o % 768;
            v = (n < 736) ? W3[k * 736 + n] : 0.f;
            ph = g_W3h; pl = g_W3l;
        }
        __nv_bfloat16 h = __float2bfloat16_rn(v);
        ph[o] = h;
        pl[o] = __float2bfloat16_rn(v - __bfloat162float(h));
    }
}

// ---------------------------------------------------------------------------
extern "C" void kernel_launch(void* const* d_in, const int* in_sizes, int n_in,
                              void* d_out, int out_size)
{
    (void)in_sizes; (void)n_in; (void)out_size;
    const float* x  = (const float*)d_in[0];
    const float* W1 = (const float*)d_in[1];
    const float* b1 = (const float*)d_in[2];
    const float* W2 = (const float*)d_in[3];
    const float* b2 = (const float*)d_in[4];
    const float* W3 = (const float*)d_in[5];
    const float* b3 = (const float*)d_in[6];
    float* out = (float*)d_out;

    prep_kernel<<<1312, 256>>>(W1, W2, W3);

    cudaFuncSetAttribute(spline_fused,
                         cudaFuncAttributeMaxDynamicSharedMemorySize, SM_TOTAL);
    spline_fused<<<B_ROWS / TM, THREADS, SM_TOTAL>>>(x, b1, b2, b3, out);
}

// round 9
// speedup vs baseline: 3.8636x; 1.7537x over previous
#include <cuda_runtime.h>
#include <cuda_bf16.h>
#include <cstdint>

// ===========================================================================
// SplineCouplingLayer — fused HMMA, W pre-packed in mma-fragment order,
// sync-free chunk loop with direct-LDG B fragments (round 9)
// ===========================================================================

#define B_ROWS  131072
#define DIM     64
#define D_IN    32
#define TAILB   3.0f

#define TM      32
#define THREADS 512

// strides (elements)
#define XT_S   33
#define XA_S   40
#define H_S    520
#define ST_S   776

// smem byte offsets
#define SM_XT    0            // 32*33*4  = 4224
#define SM_BIAS  4224         // 512*4    = 2048
#define SM_H2H   6272         // 32*520*2 = 33280
#define SM_H2L   39552
#define SM_XAH   72832        // 2560
#define SM_XAL   75392        // 2560
#define SM_H1H   77952        // 33280
#define SM_H1L   111232       // 33280 (ends 144512)
#define SM_STASH 72832        // 32*776*4 = 99328 (overlays XA/H1, ends 172160)
#define SM_TOTAL 172160

typedef unsigned int u32;

// W in fragment order: per (kc, nf) fragment, 32 lanes x uint2 {b0, b1}
// L1: K=32  -> 2 kc,  N=512 -> 64 nf
// L2: K=512 -> 32 kc, N=512 -> 64 nf
// L3: K=512 -> 32 kc, N=768 -> 96 nf (736 padded)
__device__ u32 g_F1h[2 * 64 * 64],  g_F1l[2 * 64 * 64];
__device__ u32 g_F2h[32 * 64 * 64], g_F2l[32 * 64 * 64];
__device__ u32 g_F3h[32 * 96 * 64], g_F3l[32 * 96 * 64];

__device__ __forceinline__ u32 smem_u32(const void* p) {
    u32 a;
    asm("{ .reg .u64 t; cvta.to.shared.u64 t, %1; cvt.u32.u64 %0, t; }"
        : "=r"(a) : "l"(p));
    return a;
}

#define LDSM_X4(r0, r1, r2, r3, a) \
    asm volatile("ldmatrix.sync.aligned.m8n8.x4.shared.b16 {%0,%1,%2,%3}, [%4];" \
                 : "=r"(r0), "=r"(r1), "=r"(r2), "=r"(r3) : "r"(a))

__device__ __forceinline__ void mma_bf16(float* c, const u32* a, u32 b0, u32 b1) {
    asm volatile(
        "mma.sync.aligned.m16n8k16.row.col.f32.bf16.bf16.f32 "
        "{%0,%1,%2,%3},{%4,%5,%6,%7},{%8,%9},{%0,%1,%2,%3};"
        : "+f"(c[0]), "+f"(c[1]), "+f"(c[2]), "+f"(c[3])
        : "r"(a[0]), "r"(a[1]), "r"(a[2]), "r"(a[3]), "r"(b0), "r"(b1));
}

__device__ __forceinline__ u32 pk2(__nv_bfloat16 a, __nv_bfloat16 b) {
    return (u32)__bfloat16_as_ushort(a) | ((u32)__bfloat16_as_ushort(b) << 16);
}
__device__ __forceinline__ void split2(float x, float y, u32 &hi, u32 &lo) {
    __nv_bfloat16 xh = __float2bfloat16_rn(x);
    __nv_bfloat16 yh = __float2bfloat16_rn(y);
    __nv_bfloat16 xl = __float2bfloat16_rn(x - __bfloat162float(xh));
    __nv_bfloat16 yl = __float2bfloat16_rn(y - __bfloat162float(yh));
    hi = pk2(xh, yh);
    lo = pk2(xl, yl);
}

// ---------------------------------------------------------------------------
// One layer. A: smem bf16 hi/lo [32][K] stride AS (LDSM). B: fragment-order
// global (direct LDG, prefetched). NT n-tiles (8 cols) per warp.
// ---------------------------------------------------------------------------
template<int NT, int NCH, int NFN, bool RELU, bool STASH>
__device__ __forceinline__ void do_layer(
    char* sm, u32 smb, int tid,
    const u32* __restrict__ Fh, const u32* __restrict__ Fl, int nfoff,
    const float* __restrict__ biasg, int nbias, int wcol0,
    int aoff_h, int aoff_l, int AS,
    int hoff_h, int hoff_l, int stash_col0)
{
    const int wid = tid >> 5, lane = tid & 31;
    const int nf0 = nfoff + wid * NT;

    float* bias_sm = (float*)(sm + SM_BIAS);
    for (int i = tid; i < NT * 16 * 8; i += THREADS) {
        int gc = wcol0 + i;
        bias_sm[i] = (gc < nbias) ? biasg[gc] : 0.f;
    }
    __syncthreads();   // bias visible (A already visible via caller sync)

    float acc[2][NT][4];
#pragma unroll
    for (int mt = 0; mt < 2; ++mt)
#pragma unroll
        for (int nt = 0; nt < NT; ++nt)
#pragma unroll
            for (int q = 0; q < 4; ++q) acc[mt][nt][q] = 0.f;

    u32 bh[NT][2], bl[NT][2];
    // prefetch chunk 0
#pragma unroll
    for (int nt = 0; nt < NT; ++nt) {
        uint2 vh = *((const uint2*)Fh + ((0 * NFN + nf0 + nt) * 32 + lane));
        uint2 vl = *((const uint2*)Fl + ((0 * NFN + nf0 + nt) * 32 + lane));
        bh[nt][0] = vh.x; bh[nt][1] = vh.y;
        bl[nt][0] = vl.x; bl[nt][1] = vl.y;
    }

#pragma unroll
    for (int c = 0; c < NCH; ++c) {
        u32 nh[NT][2], nl[NT][2];
        if (c + 1 < NCH) {
#pragma unroll
            for (int nt = 0; nt < NT; ++nt) {
                uint2 vh = *((const uint2*)Fh + (((c + 1) * NFN + nf0 + nt) * 32 + lane));
                uint2 vl = *((const uint2*)Fl + (((c + 1) * NFN + nf0 + nt) * 32 + lane));
                nh[nt][0] = vh.x; nh[nt][1] = vh.y;
                nl[nt][0] = vl.x; nl[nt][1] = vl.y;
            }
        }

        // A fragments (hi & lo), 2 m-tiles
        const int cK = c * 16;
        u32 ah[2][4], al[2][4];
#pragma unroll
        for (int mt = 0; mt < 2; ++mt) {
            int r  = mt * 16 + (lane & 7) + ((lane >> 3) & 1) * 8;
            int cc = cK + (lane >> 4) * 8;
            u32 off = (u32)(r * AS + cc) * 2;
            LDSM_X4(ah[mt][0], ah[mt][1], ah[mt][2], ah[mt][3], smb + aoff_h + off);
            LDSM_X4(al[mt][0], al[mt][1], al[mt][2], al[mt][3], smb + aoff_l + off);
        }

        // 3 passes: ah*bh, al*bh, ah*bl
#pragma unroll
        for (int mt = 0; mt < 2; ++mt)
#pragma unroll
            for (int nt = 0; nt < NT; ++nt)
                mma_bf16(acc[mt][nt], ah[mt], bh[nt][0], bh[nt][1]);
#pragma unroll
        for (int mt = 0; mt < 2; ++mt)
#pragma unroll
            for (int nt = 0; nt < NT; ++nt)
                mma_bf16(acc[mt][nt], al[mt], bh[nt][0], bh[nt][1]);
#pragma unroll
        for (int mt = 0; mt < 2; ++mt)
#pragma unroll
            for (int nt = 0; nt < NT; ++nt)
                mma_bf16(acc[mt][nt], ah[mt], bl[nt][0], bl[nt][1]);

        if (c + 1 < NCH) {
#pragma unroll
            for (int nt = 0; nt < NT; ++nt) {
                bh[nt][0] = nh[nt][0]; bh[nt][1] = nh[nt][1];
                bl[nt][0] = nl[nt][0]; bl[nt][1] = nl[nt][1];
            }
        }
    }

    // ---- epilogue (no sync needed: writes disjoint from other warps' reads)
    const int g  = lane >> 2;
    const int t2 = (lane & 3) * 2;
#pragma unroll
    for (int mt = 0; mt < 2; ++mt)
#pragma unroll
        for (int nt = 0; nt < NT; ++nt) {
            int col = wid * (NT * 8) + nt * 8 + t2;
            float b0v = bias_sm[col], b1v = bias_sm[col + 1];
            float v0 = acc[mt][nt][0] + b0v, v1 = acc[mt][nt][1] + b1v;
            float v2 = acc[mt][nt][2] + b0v, v3 = acc[mt][nt][3] + b1v;
            int rA = mt * 16 + g, rB = rA + 8;
            if (STASH) {
                *(float2*)(sm + SM_STASH + ((u32)rA * ST_S + stash_col0 + col) * 4)
                    = make_float2(v0, v1);
                *(float2*)(sm + SM_STASH + ((u32)rB * ST_S + stash_col0 + col) * 4)
                    = make_float2(v2, v3);
            } else {
                if (RELU) {
                    v0 = fmaxf(v0, 0.f); v1 = fmaxf(v1, 0.f);
                    v2 = fmaxf(v2, 0.f); v3 = fmaxf(v3, 0.f);
                }
                u32 h01, l01, h23, l23;
                split2(v0, v1, h01, l01);
                split2(v2, v3, h23, l23);
                u32 oA = (u32)(rA * H_S + col) * 2;
                u32 oB = (u32)(rB * H_S + col) * 2;
                *(u32*)(sm + hoff_h + oA) = h01;
                *(u32*)(sm + hoff_l + oA) = l01;
                *(u32*)(sm + hoff_h + oB) = h23;
                *(u32*)(sm + hoff_l + oB) = l23;
            }
        }
}

// ---------------------------------------------------------------------------
__device__ __forceinline__ float softplusf(float z) {
    return (z > 20.f) ? z : log1pf(expf(z));
}
__device__ __forceinline__ void spline_eval(const float raw[23], float xv,
                                            float &y_out, float &ld_out)
{
    float w[8], h[8];
    float mw = raw[0], mh = raw[8];
#pragma unroll
    for (int i = 1; i < 8; ++i) { mw = fmaxf(mw, raw[i]); mh = fmaxf(mh, raw[8 + i]); }
    float sw = 0.f, sh = 0.f;
#pragma unroll
    for (int i = 0; i < 8; ++i) {
        w[i] = expf(raw[i] - mw); sw += w[i];
        h[i] = expf(raw[8 + i] - mh); sh += h[i];
    }
    float iw = 6.f / sw, ih = 6.f / sh;
#pragma unroll
    for (int i = 0; i < 8; ++i) { w[i] *= iw; h[i] *= ih; }
    float der[9]; der[0] = 1.f; der[8] = 1.f;
#pragma unroll
    for (int i = 0; i < 7; ++i) der[i + 1] = softplusf(raw[16 + i]);
    float cw[9], ch[9]; cw[0] = -TAILB; ch[0] = -TAILB;
#pragma unroll
    for (int i = 0; i < 8; ++i) { cw[i + 1] = cw[i] + w[i]; ch[i + 1] = ch[i] + h[i]; }
    bool inside = (xv >= -TAILB) && (xv <= TAILB);
    float xc = fminf(fmaxf(xv, -TAILB + 1e-6f), TAILB - 1e-6f);
    int idx = 0;
#pragma unroll
    for (int i = 1; i <= 8; ++i) idx += (cw[i] < xc) ? 1 : 0;
    idx = min(idx, 7);
    float wk = w[0], hk = h[0], dk = der[0], dk1 = der[1], cwk = cw[0], chk = ch[0];
#pragma unroll
    for (int i = 1; i < 8; ++i) {
        bool sel = (idx == i);
        wk = sel ? w[i] : wk;   hk = sel ? h[i] : hk;
        dk = sel ? der[i] : dk; dk1 = sel ? der[i + 1] : dk1;
        cwk = sel ? cw[i] : cwk; chk = sel ? ch[i] : chk;
    }
    float xi = fminf(fmaxf((xc - cwk) / wk, 1e-6f), 1.f - 1e-6f);
    float om = 1.f - xi;
    float s = hk / wk;
    float num = hk * (s * xi * xi + dk * xi * om);
    float den = s + (dk + dk1 - 2.f * s) * xi * om;
    float yin = chk + num / den;
    float nld = s * s * (dk1 * xi * xi + 2.f * s * xi * om + dk * om * om);
    float ldin = logf(nld + 1e-8f) - logf(den * den + 1e-8f);
    y_out = inside ? yin : xv;
    ld_out = inside ? ldin : 0.f;
}

// ---------------------------------------------------------------------------
__global__ void __launch_bounds__(THREADS, 1)
spline_fused(const float* __restrict__ x,
             const float* __restrict__ b1, const float* __restrict__ b2,
             const float* __restrict__ b3, float* __restrict__ out)
{
    extern __shared__ char sm[];
    const u32 smb = smem_u32(sm);
    const int tid  = threadIdx.x;
    const int wid  = tid >> 5, lane = tid & 31;
    const int row0 = blockIdx.x * TM;

    for (int idx = tid; idx < TM * DIM; idx += THREADS) {
        int r = idx >> 6, c = idx & 63;
        float v = x[(size_t)(row0 + r) * DIM + c];
        if (c < D_IN) {
            out[(size_t)(row0 + r) * DIM + c] = v;
            __nv_bfloat16 hh = __float2bfloat16_rn(v);
            __nv_bfloat16 ll = __float2bfloat16_rn(v - __bfloat162float(hh));
            *(__nv_bfloat16*)(sm + SM_XAH + (u32)(r * XA_S + c) * 2) = hh;
            *(__nv_bfloat16*)(sm + SM_XAL + (u32)(r * XA_S + c) * 2) = ll;
        } else {
            *(float*)(sm + SM_XT + (u32)(r * XT_S + (c - D_IN)) * 4) = v;
        }
    }
    __syncthreads();

    // layer 1: K=32 (2 chunks), N=512 -> H1
    do_layer<4, 2, 64, true, false>(sm, smb, tid, g_F1h, g_F1l, 0,
                                    b1, 512, 0, SM_XAH, SM_XAL, XA_S,
                                    SM_H1H, SM_H1L, 0);
    __syncthreads();
    // layer 2: K=512 (32 chunks), N=512 -> H2
    do_layer<4, 32, 64, true, false>(sm, smb, tid, g_F2h, g_F2l, 0,
                                     b2, 512, 0, SM_H1H, SM_H1L, H_S,
                                     SM_H2H, SM_H2L, 0);
    __syncthreads();
    // layer 3: two 384-col passes -> fp32 stash
    do_layer<3, 32, 96, false, true>(sm, smb, tid, g_F3h, g_F3l, 0,
                                     b3, 736, 0, SM_H2H, SM_H2L, H_S,
                                     0, 0, 0);
    __syncthreads();
    do_layer<3, 32, 96, false, true>(sm, smb, tid, g_F3h, g_F3l, 48,
                                     b3, 736, 384, SM_H2H, SM_H2L, H_S,
                                     0, 0, 384);
    __syncthreads();

    // spline: warp w -> rows {w, w+16}
    const float* stashf = (const float*)(sm + SM_STASH);
    const float* xtf    = (const float*)(sm + SM_XT);
#pragma unroll
    for (int it = 0; it < 2; ++it) {
        int row = wid + it * 16;
        int d   = lane;
        float raw[23];
        const float* rp = stashf + (u32)row * ST_S + d * 23;
#pragma unroll
        for (int j = 0; j < 23; ++j) raw[j] = rp[j];
        float xv = xtf[row * XT_S + d];
        float yv, ld;
        spline_eval(raw, xv, yv, ld);
        int gr = row0 + row;
        out[(size_t)gr * DIM + D_IN + d] = yv;
#pragma unroll
        for (int off = 16; off; off >>= 1)
            ld += __shfl_xor_sync(0xffffffffu, ld, off);
        if (d == 0) out[(size_t)B_ROWS * DIM + gr] = ld;
    }
}

// ---------------------------------------------------------------------------
// prep: pack W into fragment-order bf16 hi/lo uint2 arrays
//   fragment (kc, nf): lane holds {b0, b1}; b0 = W[k0+2t, n], W[k0+2t+1, n]
//   with t = lane&3, n = nf*8 + (lane>>2); b1 same at k+8
// ---------------------------------------------------------------------------
__device__ __forceinline__ void frag_pack(
    const float* __restrict__ W, int N, int nvalid, int k0, int n, int t,
    u32* __restrict__ Fh, u32* __restrict__ Fl, u32 base)
{
    float w00 = 0.f, w01 = 0.f, w10 = 0.f, w11 = 0.f;
    if (n < nvalid) {
        w00 = W[(size_t)(k0 + 2 * t)     * N + n];
        w01 = W[(size_t)(k0 + 2 * t + 1) * N + n];
        w10 = W[(size_t)(k0 + 2 * t + 8) * N + n];
        w11 = W[(size_t)(k0 + 2 * t + 9) * N + n];
    }
    u32 b0h, b0l, b1h, b1l;
    split2(w00, w01, b0h, b0l);
    split2(w10, w11, b1h, b1l);
    ((uint2*)Fh)[base] = make_uint2(b0h, b1h);
    ((uint2*)Fl)[base] = make_uint2(b0l, b1l);
}

__global__ void __launch_bounds__(256)
prep_kernel(const float* __restrict__ W1, const float* __restrict__ W2,
            const float* __restrict__ W3)
{
    const int T1 = 2 * 64 * 32;     // frag-lane tasks layer 1
    const int T2 = 32 * 64 * 32;
    const int T3 = 32 * 96 * 32;
    const int TOT = T1 + T2 + T3;
    for (int id = blockIdx.x * 256 + threadIdx.x; id < TOT;
         id += gridDim.x * 256) {
        if (id < T1) {
            int lane = id & 31, fid = id >> 5;
            int nf = fid % 64, kc = fid / 64;
            frag_pack(W1, 512, 512, kc * 16, nf * 8 + (lane >> 2), lane & 3,
                      g_F1h, g_F1l, (u32)(fid * 32 + lane));
        } else if (id < T1 + T2) {
            int i = id - T1;
            int lane = i & 31, fid = i >> 5;
            int nf = fid % 64, kc = fid / 64;
            frag_pack(W2, 512, 512, kc * 16, nf * 8 + (lane >> 2), lane & 3,
                      g_F2h, g_F2l, (u32)(fid * 32 + lane));
        } else {
            int i = id - T1 - T2;
            int lane = i & 31, fid = i >> 5;
            int nf = fid % 96, kc = fid / 96;
            frag_pack(W3, 736, 736, kc * 16, nf * 8 + (lane >> 2), lane & 3,
                      g_F3h, g_F3l, (u32)(fid * 32 + lane));
        }
    }
}

// ---------------------------------------------------------------------------
extern "C" void kernel_launch(void* const* d_in, const int* in_sizes, int n_in,
                              void* d_out, int out_size)
{
    (void)in_sizes; (void)n_in; (void)out_size;
    const float* x  = (const float*)d_in[0];
    const float* W1 = (const float*)d_in[1];
    const float* b1 = (const float*)d_in[2];
    const float* W2 = (const float*)d_in[3];
    const float* b2 = (const float*)d_in[4];
    const float* W3 = (const float*)d_in[5];
    const float* b3 = (const float*)d_in[6];
    float* out = (float*)d_out;

    prep_kernel<<<656, 256>>>(W1, W2, W3);

    cudaFuncSetAttribute(spline_fused,
                         cudaFuncAttributeMaxDynamicSharedMemorySize, SM_TOTAL);
    spline_fused<<<B_ROWS / TM, THREADS, SM_TOTAL>>>(x, b1, b2, b3, out);
}

// round 10
// speedup vs baseline: 3.8723x; 1.0023x over previous
#include <cuda_runtime.h>
#include <cuda_bf16.h>
#include <cstdint>

// ===========================================================================
// SplineCouplingLayer — fused HMMA (round 10)
//  - B fragments interleaved hi/lo -> single LDG.128 each
//  - L2: A + B double-buffered chunk loop
//  - L3: one chunk loop, both N-halves per A load
//  - biases preloaded once
// ===========================================================================

#define B_ROWS  131072
#define DIM     64
#define D_IN    32
#define TAILB   3.0f

#define TM      32
#define THREADS 512

// strides (elements)
#define XT_S   33
#define XA_S   40
#define H_S    520
#define ST_S   776

// smem byte offsets
#define SM_XT    0            // 32*33*4  = 4224
#define SM_BIAS  4224         // 1792*4   = 7168
#define SM_H2H   11392        // 32*520*2 = 33280
#define SM_H2L   44672        // 33280
#define SM_XAH   77952        // 2560
#define SM_XAL   80512        // 2560
#define SM_H1H   83072        // 33280
#define SM_H1L   116352       // 33280 (ends 149632)
#define SM_STASH 77952        // 32*776*4 = 99328 (overlays XA/H1, ends 177280)
#define SM_TOTAL 177280

typedef unsigned int u32;

// W fragments interleaved: per (kc, nf): 32 lanes x uint4 {b0h, b1h, b0l, b1l}
__device__ u32 g_F1[2 * 64 * 32 * 4];
__device__ u32 g_F2[32 * 64 * 32 * 4];
__device__ u32 g_F3[32 * 96 * 32 * 4];

__device__ __forceinline__ u32 smem_u32(const void* p) {
    u32 a;
    asm("{ .reg .u64 t; cvta.to.shared.u64 t, %1; cvt.u32.u64 %0, t; }"
        : "=r"(a) : "l"(p));
    return a;
}

#define LDSM_X4(r0, r1, r2, r3, a) \
    asm volatile("ldmatrix.sync.aligned.m8n8.x4.shared.b16 {%0,%1,%2,%3}, [%4];" \
                 : "=r"(r0), "=r"(r1), "=r"(r2), "=r"(r3) : "r"(a))

__device__ __forceinline__ void mma_bf16(float* c, const u32* a, u32 b0, u32 b1) {
    asm volatile(
        "mma.sync.aligned.m16n8k16.row.col.f32.bf16.bf16.f32 "
        "{%0,%1,%2,%3},{%4,%5,%6,%7},{%8,%9},{%0,%1,%2,%3};"
        : "+f"(c[0]), "+f"(c[1]), "+f"(c[2]), "+f"(c[3])
        : "r"(a[0]), "r"(a[1]), "r"(a[2]), "r"(a[3]), "r"(b0), "r"(b1));
}

__device__ __forceinline__ u32 pk2(__nv_bfloat16 a, __nv_bfloat16 b) {
    return (u32)__bfloat16_as_ushort(a) | ((u32)__bfloat16_as_ushort(b) << 16);
}
__device__ __forceinline__ void split2(float x, float y, u32 &hi, u32 &lo) {
    __nv_bfloat16 xh = __float2bfloat16_rn(x);
    __nv_bfloat16 yh = __float2bfloat16_rn(y);
    __nv_bfloat16 xl = __float2bfloat16_rn(x - __bfloat162float(xh));
    __nv_bfloat16 yl = __float2bfloat16_rn(y - __bfloat162float(yh));
    hi = pk2(xh, yh);
    lo = pk2(xl, yl);
}

// load A hi/lo fragments for chunk with k offset cK
__device__ __forceinline__ void load_afrag(
    u32 smb, int aoff_h, int aoff_l, int AS, int lane, int cK,
    u32 ah[2][4], u32 al[2][4])
{
#pragma unroll
    for (int mt = 0; mt < 2; ++mt) {
        int r  = mt * 16 + (lane & 7) + ((lane >> 3) & 1) * 8;
        int cc = cK + (lane >> 4) * 8;
        u32 off = (u32)(r * AS + cc) * 2;
        LDSM_X4(ah[mt][0], ah[mt][1], ah[mt][2], ah[mt][3], smb + aoff_h + off);
        LDSM_X4(al[mt][0], al[mt][1], al[mt][2], al[mt][3], smb + aoff_l + off);
    }
}

// ---------------------------------------------------------------------------
// Layers 1/2: NT n-tiles per warp, single N pass, A+B double-buffered.
// ---------------------------------------------------------------------------
template<int NT, int NCH, int NFN, bool RELU>
__device__ __forceinline__ void do_layer_lin(
    char* sm, u32 smb, int tid, const u32* __restrict__ F, int bias_off,
    int aoff_h, int aoff_l, int AS, int hoff_h, int hoff_l)
{
    const int wid = tid >> 5, lane = tid & 31;
    const int nf0 = wid * NT;
    const uint4* Fq = (const uint4*)F;
    const float* bias_sm = (const float*)(sm + SM_BIAS) + bias_off;

    float acc[2][NT][4];
#pragma unroll
    for (int mt = 0; mt < 2; ++mt)
#pragma unroll
        for (int nt = 0; nt < NT; ++nt)
#pragma unroll
            for (int q = 0; q < 4; ++q) acc[mt][nt][q] = 0.f;

    uint4 bcur[NT], bnext[NT];
    u32 ahc[2][4], alc[2][4], ahn[2][4], aln[2][4];
#pragma unroll
    for (int nt = 0; nt < NT; ++nt)
        bcur[nt] = Fq[(0 * NFN + nf0 + nt) * 32 + lane];
    load_afrag(smb, aoff_h, aoff_l, AS, lane, 0, ahc, alc);

#pragma unroll
    for (int c = 0; c < NCH; ++c) {
        if (c + 1 < NCH) {
#pragma unroll
            for (int nt = 0; nt < NT; ++nt)
                bnext[nt] = Fq[((c + 1) * NFN + nf0 + nt) * 32 + lane];
            load_afrag(smb, aoff_h, aoff_l, AS, lane, (c + 1) * 16, ahn, aln);
        }
#pragma unroll
        for (int mt = 0; mt < 2; ++mt)
#pragma unroll
            for (int nt = 0; nt < NT; ++nt)
                mma_bf16(acc[mt][nt], ahc[mt], bcur[nt].x, bcur[nt].y);
#pragma unroll
        for (int mt = 0; mt < 2; ++mt)
#pragma unroll
            for (int nt = 0; nt < NT; ++nt)
                mma_bf16(acc[mt][nt], alc[mt], bcur[nt].x, bcur[nt].y);
#pragma unroll
        for (int mt = 0; mt < 2; ++mt)
#pragma unroll
            for (int nt = 0; nt < NT; ++nt)
                mma_bf16(acc[mt][nt], ahc[mt], bcur[nt].z, bcur[nt].w);

        if (c + 1 < NCH) {
#pragma unroll
            for (int nt = 0; nt < NT; ++nt) bcur[nt] = bnext[nt];
#pragma unroll
            for (int mt = 0; mt < 2; ++mt)
#pragma unroll
                for (int q = 0; q < 4; ++q) {
                    ahc[mt][q] = ahn[mt][q];
                    alc[mt][q] = aln[mt][q];
                }
        }
    }

    const int g  = lane >> 2;
    const int t2 = (lane & 3) * 2;
#pragma unroll
    for (int mt = 0; mt < 2; ++mt)
#pragma unroll
        for (int nt = 0; nt < NT; ++nt) {
            int col = wid * (NT * 8) + nt * 8 + t2;
            float b0v = bias_sm[col], b1v = bias_sm[col + 1];
            float v0 = acc[mt][nt][0] + b0v, v1 = acc[mt][nt][1] + b1v;
            float v2 = acc[mt][nt][2] + b0v, v3 = acc[mt][nt][3] + b1v;
            if (RELU) {
                v0 = fmaxf(v0, 0.f); v1 = fmaxf(v1, 0.f);
                v2 = fmaxf(v2, 0.f); v3 = fmaxf(v3, 0.f);
            }
            u32 h01, l01, h23, l23;
            split2(v0, v1, h01, l01);
            split2(v2, v3, h23, l23);
            int rA = mt * 16 + g, rB = rA + 8;
            u32 oA = (u32)(rA * H_S + col) * 2;
            u32 oB = (u32)(rB * H_S + col) * 2;
            *(u32*)(sm + hoff_h + oA) = h01;
            *(u32*)(sm + hoff_l + oA) = l01;
            *(u32*)(sm + hoff_h + oB) = h23;
            *(u32*)(sm + hoff_l + oB) = l23;
        }
}

// ---------------------------------------------------------------------------
// Layer 3: NT=3, both 384-col halves per A load -> fp32 stash.
// ---------------------------------------------------------------------------
__device__ __forceinline__ void do_layer3(
    char* sm, u32 smb, int tid, const u32* __restrict__ F,
    int aoff_h, int aoff_l, int AS)
{
    const int wid = tid >> 5, lane = tid & 31;
    const int nf0 = wid * 3;
    const uint4* Fq = (const uint4*)F;
    const float* bias_sm = (const float*)(sm + SM_BIAS) + 1024;

    float acc[2][2][3][4];      // [half][mt][nt][4]
#pragma unroll
    for (int hh = 0; hh < 2; ++hh)
#pragma unroll
        for (int mt = 0; mt < 2; ++mt)
#pragma unroll
            for (int nt = 0; nt < 3; ++nt)
#pragma unroll
                for (int q = 0; q < 4; ++q) acc[hh][mt][nt][q] = 0.f;

    uint4 bcur[3], bnext[3];
    u32 ah[2][4], al[2][4];
#pragma unroll
    for (int nt = 0; nt < 3; ++nt)
        bcur[nt] = Fq[(0 * 96 + nf0 + nt) * 32 + lane];

#pragma unroll
    for (int c = 0; c < 32; ++c) {
        load_afrag(smb, aoff_h, aoff_l, AS, lane, c * 16, ah, al);

        // half 0 (prefetch half 1 of same chunk)
#pragma unroll
        for (int nt = 0; nt < 3; ++nt)
            bnext[nt] = Fq[(c * 96 + 48 + nf0 + nt) * 32 + lane];
#pragma unroll
        for (int mt = 0; mt < 2; ++mt)
#pragma unroll
            for (int nt = 0; nt < 3; ++nt)
                mma_bf16(acc[0][mt][nt], ah[mt], bcur[nt].x, bcur[nt].y);
#pragma unroll
        for (int mt = 0; mt < 2; ++mt)
#pragma unroll
            for (int nt = 0; nt < 3; ++nt)
                mma_bf16(acc[0][mt][nt], al[mt], bcur[nt].x, bcur[nt].y);
#pragma unroll
        for (int mt = 0; mt < 2; ++mt)
#pragma unroll
            for (int nt = 0; nt < 3; ++nt)
                mma_bf16(acc[0][mt][nt], ah[mt], bcur[nt].z, bcur[nt].w);
#pragma unroll
        for (int nt = 0; nt < 3; ++nt) bcur[nt] = bnext[nt];

        // half 1 (prefetch half 0 of next chunk)
        if (c + 1 < 32) {
#pragma unroll
            for (int nt = 0; nt < 3; ++nt)
                bnext[nt] = Fq[((c + 1) * 96 + nf0 + nt) * 32 + lane];
        }
#pragma unroll
        for (int mt = 0; mt < 2; ++mt)
#pragma unroll
            for (int nt = 0; nt < 3; ++nt)
                mma_bf16(acc[1][mt][nt], ah[mt], bcur[nt].x, bcur[nt].y);
#pragma unroll
        for (int mt = 0; mt < 2; ++mt)
#pragma unroll
            for (int nt = 0; nt < 3; ++nt)
                mma_bf16(acc[1][mt][nt], al[mt], bcur[nt].x, bcur[nt].y);
#pragma unroll
        for (int mt = 0; mt < 2; ++mt)
#pragma unroll
            for (int nt = 0; nt < 3; ++nt)
                mma_bf16(acc[1][mt][nt], ah[mt], bcur[nt].z, bcur[nt].w);
        if (c + 1 < 32) {
#pragma unroll
            for (int nt = 0; nt < 3; ++nt) bcur[nt] = bnext[nt];
        }
    }

    const int g  = lane >> 2;
    const int t2 = (lane & 3) * 2;
#pragma unroll
    for (int hh = 0; hh < 2; ++hh)
#pragma unroll
        for (int mt = 0; mt < 2; ++mt)
#pragma unroll
            for (int nt = 0; nt < 3; ++nt) {
                int col  = wid * 24 + nt * 8 + t2;
                int scol = hh * 384 + col;
                float b0v = bias_sm[scol], b1v = bias_sm[scol + 1];
                float v0 = acc[hh][mt][nt][0] + b0v;
                float v1 = acc[hh][mt][nt][1] + b1v;
                float v2 = acc[hh][mt][nt][2] + b0v;
                float v3 = acc[hh][mt][nt][3] + b1v;
                int rA = mt * 16 + g, rB = rA + 8;
                *(float2*)(sm + SM_STASH + ((u32)rA * ST_S + scol) * 4)
                    = make_float2(v0, v1);
                *(float2*)(sm + SM_STASH + ((u32)rB * ST_S + scol) * 4)
                    = make_float2(v2, v3);
            }
}

// ---------------------------------------------------------------------------
__device__ __forceinline__ float softplusf(float z) {
    return (z > 20.f) ? z : log1pf(expf(z));
}
__device__ __forceinline__ void spline_eval(const float raw[23], float xv,
                                            float &y_out, float &ld_out)
{
    float w[8], h[8];
    float mw = raw[0], mh = raw[8];
#pragma unroll
    for (int i = 1; i < 8; ++i) { mw = fmaxf(mw, raw[i]); mh = fmaxf(mh, raw[8 + i]); }
    float sw = 0.f, sh = 0.f;
#pragma unroll
    for (int i = 0; i < 8; ++i) {
        w[i] = expf(raw[i] - mw); sw += w[i];
        h[i] = expf(raw[8 + i] - mh); sh += h[i];
    }
    float iw = 6.f / sw, ih = 6.f / sh;
#pragma unroll
    for (int i = 0; i < 8; ++i) { w[i] *= iw; h[i] *= ih; }
    float der[9]; der[0] = 1.f; der[8] = 1.f;
#pragma unroll
    for (int i = 0; i < 7; ++i) der[i + 1] = softplusf(raw[16 + i]);
    float cw[9], ch[9]; cw[0] = -TAILB; ch[0] = -TAILB;
#pragma unroll
    for (int i = 0; i < 8; ++i) { cw[i + 1] = cw[i] + w[i]; ch[i + 1] = ch[i] + h[i]; }
    bool inside = (xv >= -TAILB) && (xv <= TAILB);
    float xc = fminf(fmaxf(xv, -TAILB + 1e-6f), TAILB - 1e-6f);
    int idx = 0;
#pragma unroll
    for (int i = 1; i <= 8; ++i) idx += (cw[i] < xc) ? 1 : 0;
    idx = min(idx, 7);
    float wk = w[0], hk = h[0], dk = der[0], dk1 = der[1], cwk = cw[0], chk = ch[0];
#pragma unroll
    for (int i = 1; i < 8; ++i) {
        bool sel = (idx == i);
        wk = sel ? w[i] : wk;   hk = sel ? h[i] : hk;
        dk = sel ? der[i] : dk; dk1 = sel ? der[i + 1] : dk1;
        cwk = sel ? cw[i] : cwk; chk = sel ? ch[i] : chk;
    }
    float xi = fminf(fmaxf((xc - cwk) / wk, 1e-6f), 1.f - 1e-6f);
    float om = 1.f - xi;
    float s = hk / wk;
    float num = hk * (s * xi * xi + dk * xi * om);
    float den = s + (dk + dk1 - 2.f * s) * xi * om;
    float yin = chk + num / den;
    float nld = s * s * (dk1 * xi * xi + 2.f * s * xi * om + dk * om * om);
    float ldin = logf(nld + 1e-8f) - logf(den * den + 1e-8f);
    y_out = inside ? yin : xv;
    ld_out = inside ? ldin : 0.f;
}

// ---------------------------------------------------------------------------
__global__ void __launch_bounds__(THREADS, 1)
spline_fused(const float* __restrict__ x,
             const float* __restrict__ b1, const float* __restrict__ b2,
             const float* __restrict__ b3, float* __restrict__ out)
{
    extern __shared__ char sm[];
    const u32 smb = smem_u32(sm);
    const int tid  = threadIdx.x;
    const int wid  = tid >> 5, lane = tid & 31;
    const int row0 = blockIdx.x * TM;

    // preload all biases (1792 floats)
    {
        float* bias_sm = (float*)(sm + SM_BIAS);
        for (int i = tid; i < 1792; i += THREADS) {
            float v;
            if (i < 512)       v = b1[i];
            else if (i < 1024) v = b2[i - 512];
            else { int j = i - 1024; v = (j < 736) ? b3[j] : 0.f; }
            bias_sm[i] = v;
        }
    }
    // x tile: masked -> XA hi/lo + passthrough; transform -> XT
    for (int idx = tid; idx < TM * DIM; idx += THREADS) {
        int r = idx >> 6, c = idx & 63;
        float v = x[(size_t)(row0 + r) * DIM + c];
        if (c < D_IN) {
            out[(size_t)(row0 + r) * DIM + c] = v;
            __nv_bfloat16 hh = __float2bfloat16_rn(v);
            __nv_bfloat16 ll = __float2bfloat16_rn(v - __bfloat162float(hh));
            *(__nv_bfloat16*)(sm + SM_XAH + (u32)(r * XA_S + c) * 2) = hh;
            *(__nv_bfloat16*)(sm + SM_XAL + (u32)(r * XA_S + c) * 2) = ll;
        } else {
            *(float*)(sm + SM_XT + (u32)(r * XT_S + (c - D_IN)) * 4) = v;
        }
    }
    __syncthreads();

    do_layer_lin<4, 2, 64, true>(sm, smb, tid, g_F1, 0,
                                 SM_XAH, SM_XAL, XA_S, SM_H1H, SM_H1L);
    __syncthreads();
    do_layer_lin<4, 32, 64, true>(sm, smb, tid, g_F2, 512,
                                  SM_H1H, SM_H1L, H_S, SM_H2H, SM_H2L);
    __syncthreads();
    do_layer3(sm, smb, tid, g_F3, SM_H2H, SM_H2L, H_S);
    __syncthreads();

    // spline: warp w -> rows {w, w+16}
    const float* stashf = (const float*)(sm + SM_STASH);
    const float* xtf    = (const float*)(sm + SM_XT);
#pragma unroll
    for (int it = 0; it < 2; ++it) {
        int row = wid + it * 16;
        int d   = lane;
        float raw[23];
        const float* rp = stashf + (u32)row * ST_S + d * 23;
#pragma unroll
        for (int j = 0; j < 23; ++j) raw[j] = rp[j];
        float xv = xtf[row * XT_S + d];
        float yv, ld;
        spline_eval(raw, xv, yv, ld);
        int gr = row0 + row;
        out[(size_t)gr * DIM + D_IN + d] = yv;
#pragma unroll
        for (int off = 16; off; off >>= 1)
            ld += __shfl_xor_sync(0xffffffffu, ld, off);
        if (d == 0) out[(size_t)B_ROWS * DIM + gr] = ld;
    }
}

// ---------------------------------------------------------------------------
// prep: pack W into interleaved fragment-order uint4 {b0h, b1h, b0l, b1l}
// ---------------------------------------------------------------------------
__device__ __forceinline__ void frag_pack(
    const float* __restrict__ W, int N, int nvalid, int k0, int n, int t,
    u32* __restrict__ F, u32 base)
{
    float w00 = 0.f, w01 = 0.f, w10 = 0.f, w11 = 0.f;
    if (n < nvalid) {
        w00 = W[(size_t)(k0 + 2 * t)     * N + n];
        w01 = W[(size_t)(k0 + 2 * t + 1) * N + n];
        w10 = W[(size_t)(k0 + 2 * t + 8) * N + n];
        w11 = W[(size_t)(k0 + 2 * t + 9) * N + n];
    }
    u32 b0h, b0l, b1h, b1l;
    split2(w00, w01, b0h, b0l);
    split2(w10, w11, b1h, b1l);
    ((uint4*)F)[base] = make_uint4(b0h, b1h, b0l, b1l);
}

__global__ void __launch_bounds__(256)
prep_kernel(const float* __restrict__ W1, const float* __restrict__ W2,
            const float* __restrict__ W3)
{
    const int T1 = 2 * 64 * 32;
    const int T2 = 32 * 64 * 32;
    const int T3 = 32 * 96 * 32;
    const int TOT = T1 + T2 + T3;
    for (int id = blockIdx.x * 256 + threadIdx.x; id < TOT;
         id += gridDim.x * 256) {
        if (id < T1) {
            int lane = id & 31, fid = id >> 5;
            int nf = fid % 64, kc = fid / 64;
            frag_pack(W1, 512, 512, kc * 16, nf * 8 + (lane >> 2), lane & 3,
                      g_F1, (u32)(fid * 32 + lane));
        } else if (id < T1 + T2) {
            int i = id - T1;
            int lane = i & 31, fid = i >> 5;
            int nf = fid % 64, kc = fid / 64;
            frag_pack(W2, 512, 512, kc * 16, nf * 8 + (lane >> 2), lane & 3,
                      g_F2, (u32)(fid * 32 + lane));
        } else {
            int i = id - T1 - T2;
            int lane = i & 31, fid = i >> 5;
            int nf = fid % 96, kc = fid / 96;
            frag_pack(W3, 736, 736, kc * 16, nf * 8 + (lane >> 2), lane & 3,
                      g_F3, (u32)(fid * 32 + lane));
        }
    }
}

// ---------------------------------------------------------------------------
extern "C" void kernel_launch(void* const* d_in, const int* in_sizes, int n_in,
                              void* d_out, int out_size)
{
    (void)in_sizes; (void)n_in; (void)out_size;
    const float* x  = (const float*)d_in[0];
    const float* W1 = (const float*)d_in[1];
    const float* b1 = (const float*)d_in[2];
    const float* W2 = (const float*)d_in[3];
    const float* b2 = (const float*)d_in[4];
    const float* W3 = (const float*)d_in[5];
    const float* b3 = (const float*)d_in[6];
    float* out = (float*)d_out;

    prep_kernel<<<656, 256>>>(W1, W2, W3);

    cudaFuncSetAttribute(spline_fused,
                         cudaFuncAttributeMaxDynamicSharedMemorySize, SM_TOTAL);
    spline_fused<<<B_ROWS / TM, THREADS, SM_TOTAL>>>(x, b1, b2, b3, out);
}